// round 3
// baseline (speedup 1.0000x reference)
#include <cuda_runtime.h>

#define BB 1024
#define DD 256
#define HH 32

// exp(+W)/exp(-W), interleaved by j-pair: float2 element [pr*DD + d] holds
// (exp(s*W[d, 2*pr]), exp(s*W[d, 2*pr+1])) -> one coalesced LDG.64 per 2 factors.
__device__ float g_ewp[HH * DD];
__device__ float g_ewm[HH * DD];
__device__ float2 g_eb[DD];          // (exp(+b/2), exp(-b/2))

__global__ void precompute_kernel(const float* __restrict__ W,
                                  const float* __restrict__ b) {
    int i = blockIdx.x * blockDim.x + threadIdx.x;
    if (i < DD * HH) {
        int d = i >> 5;       // row in W [D, H]
        int j = i & 31;       // col in W
        float w = W[i];
        int idx = (j >> 1) * (DD * 2) + d * 2 + (j & 1);
        g_ewp[idx] = expf(w);
        g_ewm[idx] = expf(-w);
    }
    if (i < DD) {
        float bv = b[i];
        g_eb[i] = make_float2(expf(0.5f * bv), expf(-0.5f * bv));
    }
}

__device__ __forceinline__ unsigned fmono(float f) {
    unsigned u = __float_as_uint(f);
    return (u & 0x80000000u) ? ~u : (u | 0x80000000u);
}

__global__ __launch_bounds__(256) void gwg_kernel(
    const float* __restrict__ x,
    const float* __restrict__ W,
    const float* __restrict__ c,
    const float* __restrict__ gum,
    const float* __restrict__ acc,
    float* __restrict__ out)
{
    __shared__ __align__(16) float  xs[DD];
    __shared__ float  ap[8][32];
    __shared__ __align__(16) float2 sC[HH];   // (sigmoid(a_j), sigmoid(-a_j))
    __shared__ float    redf[8];
    __shared__ unsigned redk[8];
    __shared__ int      redi[8];

    const int row  = blockIdx.x;
    const int tid  = threadIdx.x;
    const int w    = tid >> 5;
    const int lane = tid & 31;
    const int k    = tid;

    // hoist all per-row scalars
    float  xk  = x[row * DD + k];
    float2 ebv = g_eb[k];
    float  u   = gum[row * DD + k];
    float  au  = acc[row];
    xs[k] = xk;
    __syncwarp();   // warp w only reads its own xs slice below

    // ---- a_j partials: warp w covers d in [w*32, w*32+32), lane = j ----
    {
        float part = 0.f;
        const int base = w * 32;
        const float4* xv4 = (const float4*)(xs + base);
        #pragma unroll
        for (int q = 0; q < 8; ++q) {
            float4 xv = xv4[q];
            int d = base + q * 4;
            part = fmaf(xv.x, W[(d + 0) * HH + lane], part);
            part = fmaf(xv.y, W[(d + 1) * HH + lane], part);
            part = fmaf(xv.z, W[(d + 2) * HH + lane], part);
            part = fmaf(xv.w, W[(d + 3) * HH + lane], part);
        }
        ap[w][lane] = part;
    }
    __syncthreads();                       // B1

    float E = 0.f;                         // exp(a_lane), valid in warp 0 only
    if (w == 0) {
        float a = c[lane];
        #pragma unroll
        for (int ww = 0; ww < 8; ++ww) a += ap[ww][lane];
        E = expf(a);
        float inv = 1.0f / (1.0f + E);
        sC[lane] = make_float2(E * inv, inv);
    }
    __syncthreads();                       // B2

    // ---- forward: ek = exp(b_k*delta/2) * sqrt(prod_j (EI_j e^{delta w} + I_j)) ----
    const float2* ewT = (const float2*)((xk == 0.0f) ? g_ewp : g_ewm);
    const float   eb  = (xk == 0.0f) ? ebv.x : ebv.y;
    const float4* sC4 = (const float4*)sC;

    float p0 = 1.f, p1 = 1.f, p2 = 1.f, p3 = 1.f;
    #pragma unroll
    for (int jp = 0; jp < 16; jp += 2) {
        float4 cA = sC4[jp];
        float4 cB = sC4[jp + 1];
        float2 eA = __ldg(&ewT[jp * DD + k]);
        float2 eB = __ldg(&ewT[(jp + 1) * DD + k]);
        p0 *= fmaf(cA.x, eA.x, cA.y);
        p1 *= fmaf(cA.z, eA.y, cA.w);
        p2 *= fmaf(cB.x, eB.x, cB.y);
        p3 *= fmaf(cB.z, eB.y, cB.w);
    }
    float p  = (p0 * p1) * (p2 * p3);
    float ek = eb * sqrtf(p);

    // gumbel-max in exp domain: argmax(l+g) == argmax(ek / z), z = -log(u+eps)+eps
    float z   = -logf(u + 1e-9f) + 1e-9f;
    float key = ek / z;

    // ---- warp reduce: sum(ek), argmax(key) [tie -> lowest k] ----
    float s = ek;
    #pragma unroll
    for (int off = 16; off; off >>= 1) s += __shfl_xor_sync(0xffffffffu, s, off);
    unsigned km   = fmono(key);
    unsigned wmax = __reduce_max_sync(0xffffffffu, km);
    unsigned ball = __ballot_sync(0xffffffffu, km == wmax);
    if (lane == 0) {
        redf[w] = s;
        redk[w] = wmax;
        redi[w] = w * 32 + (__ffs(ball) - 1);
    }
    __syncthreads();                       // B3

    // ---- every warp redundantly combines -> Zf, kstar in registers ----
    float Zf;
    int   kstar;
    {
        float    Zv = (lane < 8) ? redf[lane] : 0.f;
        unsigned kv = (lane < 8) ? redk[lane] : 0u;
        int      ri = (lane < 8) ? redi[lane] : 0;
        #pragma unroll
        for (int off = 16; off; off >>= 1) Zv += __shfl_xor_sync(0xffffffffu, Zv, off);
        Zf = Zv;
        unsigned mx = __reduce_max_sync(0xffffffffu, kv);
        unsigned bl = __ballot_sync(0xffffffffu, kv == mx);
        int srcw = __ffs(bl) - 1;          // lowest warp with max -> lowest k
        kstar = __shfl_sync(0xffffffffu, ri, srcw);
    }

    // ---- warp 0: rank-1 sigmoid update for the flipped state ----
    if (w == 0) {
        float xks = xs[kstar];
        const float2* t2 = (const float2*)((xks == 0.0f) ? g_ewp : g_ewm);
        float2 pr = __ldg(&t2[(lane >> 1) * DD + kstar]);
        float m    = (lane & 1) ? pr.y : pr.x;
        float E2   = E * m;
        float inv2 = 1.0f / (1.0f + E2);
        sC[lane] = make_float2(E2 * inv2, inv2);
    }
    __syncthreads();                       // B4

    // ---- reverse pass at x_delta ----
    float xk2 = (k == kstar) ? 1.f - xk : xk;
    const float2* ewT3 = (const float2*)((xk2 == 0.0f) ? g_ewp : g_ewm);
    const float   eb2  = (xk2 == 0.0f) ? ebv.x : ebv.y;

    float q0 = 1.f, q1 = 1.f, q2 = 1.f, q3 = 1.f;
    #pragma unroll
    for (int jp = 0; jp < 16; jp += 2) {
        float4 cA = sC4[jp];
        float4 cB = sC4[jp + 1];
        float2 eA = __ldg(&ewT3[jp * DD + k]);
        float2 eB = __ldg(&ewT3[(jp + 1) * DD + k]);
        q0 *= fmaf(cA.x, eA.x, cA.y);
        q1 *= fmaf(cA.z, eA.y, cA.w);
        q2 *= fmaf(cB.x, eB.x, cB.y);
        q3 *= fmaf(cB.z, eB.y, cB.w);
    }
    float q   = (q0 * q1) * (q2 * q3);
    float ek2 = eb2 * sqrtf(q);

    float s2 = ek2;
    #pragma unroll
    for (int off = 16; off; off >>= 1) s2 += __shfl_xor_sync(0xffffffffu, s2, off);
    if (lane == 0) redf[w] = s2;
    __syncthreads();                       // B5

    float Zr;
    {
        float Zv = (lane < 8) ? redf[lane] : 0.f;
        #pragma unroll
        for (int off = 16; off; off >>= 1) Zv += __shfl_xor_sync(0xffffffffu, Zv, off);
        Zr = Zv;
    }

    // ---- accept / reject, write row ----
    bool  accv  = (Zf / Zr) > au;
    float out_k = (k == kstar && accv) ? (1.f - xk) : xk;
    out[row * DD + k] = out_k;
}

extern "C" void kernel_launch(void* const* d_in, const int* in_sizes, int n_in,
                              void* d_out, int out_size) {
    const float* x   = (const float*)d_in[0];
    const float* W   = (const float*)d_in[1];
    const float* b   = (const float*)d_in[2];
    const float* c   = (const float*)d_in[3];
    const float* gum = (const float*)d_in[4];
    const float* acc = (const float*)d_in[5];
    float* out = (float*)d_out;

    precompute_kernel<<<(DD * HH + 255) / 256, 256>>>(W, b);
    gwg_kernel<<<BB, 256>>>(x, W, c, gum, acc, out);
}

// round 4
// speedup vs baseline: 1.1685x; 1.1685x over previous
#include <cuda_runtime.h>

#define BB 1024
#define DD 256
#define HH 32

// exp(+W)/exp(-W), interleaved by j-pair: float2 element [pr*DD + d] holds
// (exp(s*W[d, 2*pr]), exp(s*W[d, 2*pr+1])) -> one coalesced LDG.64 per 2 factors.
__device__ float g_ewp[HH * DD];
__device__ float g_ewm[HH * DD];
__device__ float2 g_eb[DD];          // (exp(+b/2), exp(-b/2))

__global__ void precompute_kernel(const float* __restrict__ W,
                                  const float* __restrict__ b) {
    int i = blockIdx.x * blockDim.x + threadIdx.x;
    if (i < DD * HH) {
        int d = i >> 5;
        int j = i & 31;
        float w = W[i];
        int idx = (j >> 1) * (DD * 2) + d * 2 + (j & 1);
        g_ewp[idx] = expf(w);
        g_ewm[idx] = expf(-w);
    }
    if (i < DD) {
        float bv = b[i];
        g_eb[i] = make_float2(expf(0.5f * bv), expf(-0.5f * bv));
    }
}

__device__ __forceinline__ unsigned fmono(float f) {
    unsigned u = __float_as_uint(f);
    return (u & 0x80000000u) ? ~u : (u | 0x80000000u);
}

__global__ __launch_bounds__(256, 4) void gwg_kernel(
    const float* __restrict__ x,
    const float* __restrict__ W,
    const float* __restrict__ c,
    const float* __restrict__ gum,
    const float* __restrict__ acc,
    float* __restrict__ out)
{
    __shared__ float  xs[DD];
    __shared__ float  ap[8][32];
    __shared__ __align__(16) float sEf[HH];   // E_j  = exp(a_j)
    __shared__ __align__(16) float sE2[HH];   // E'_j = exp(a'_j) after rank-1 update
    __shared__ float    redf[8];
    __shared__ unsigned redk[8];
    __shared__ int      redi[8];
    __shared__ float    sRt;                  // prod_j (1+E'_j)/(1+E_j)

    const int row  = blockIdx.x;
    const int tid  = threadIdx.x;
    const int w    = tid >> 5;
    const int lane = tid & 31;
    const int k    = tid;

    float  xk  = x[row * DD + k];
    float2 ebv = g_eb[k];
    float  u   = gum[row * DD + k];
    float  au  = acc[row];
    xs[k] = xk;

    // ---- a_j partials: warp w covers d-chunk [w*32, w*32+32), lane = j ----
    // x is binary -> ballot mask; predicated-off LDGs generate no L1 traffic.
    {
        unsigned m = __ballot_sync(0xffffffffu, xk != 0.0f);
        const float* Wb = W + (w * 32) * HH + lane;
        float pa = 0.f, pb = 0.f;
        #pragma unroll
        for (int i = 0; i < 32; i += 2) {
            if (m & (1u << i))       pa += Wb[i * HH];
            if (m & (1u << (i + 1))) pb += Wb[(i + 1) * HH];
        }
        ap[w][lane] = pa + pb;
    }
    __syncthreads();                       // B1

    float E = 0.f;                         // exp(a_lane), warp 0 only
    if (w == 0) {
        float a = c[lane];
        #pragma unroll
        for (int ww = 0; ww < 8; ++ww) a += ap[ww][lane];
        E = expf(a);
        sEf[lane] = E;
    }
    __syncthreads();                       // B2

    // ---- forward: p~_k = prod_j (1 + E_j e^{delta w});  ek = eb * sqrt(p~) ----
    const float2* ewT = (const float2*)((xk == 0.0f) ? g_ewp : g_ewm);
    const float   eb  = (xk == 0.0f) ? ebv.x : ebv.y;
    const float4* sE4f = (const float4*)sEf;

    float2 ec[16];                          // cached table row: reused in reverse pass
    #pragma unroll
    for (int jp = 0; jp < 16; ++jp) ec[jp] = __ldg(&ewT[jp * DD + k]);

    float p0 = 1.f, p1 = 1.f, p2 = 1.f, p3 = 1.f;
    #pragma unroll
    for (int jp = 0; jp < 16; jp += 2) {
        float4 Ev = sE4f[jp >> 1];          // E for j = 2*jp .. 2*jp+3
        p0 *= fmaf(Ev.x, ec[jp].x,     1.f);
        p1 *= fmaf(Ev.y, ec[jp].y,     1.f);
        p2 *= fmaf(Ev.z, ec[jp + 1].x, 1.f);
        p3 *= fmaf(Ev.w, ec[jp + 1].y, 1.f);
    }
    float p  = (p0 * p1) * (p2 * p3);
    float ek = eb * sqrtf(p);

    // gumbel-max in exp domain: argmax(l+g) == argmax(ek / z)
    float z   = -logf(u + 1e-9f) + 1e-9f;
    float key = ek / z;

    // ---- warp reduce: sum(ek), argmax(key) [tie -> lowest k] ----
    float s = ek;
    #pragma unroll
    for (int off = 16; off; off >>= 1) s += __shfl_xor_sync(0xffffffffu, s, off);
    unsigned km   = fmono(key);
    unsigned wmax = __reduce_max_sync(0xffffffffu, km);
    unsigned ball = __ballot_sync(0xffffffffu, km == wmax);
    if (lane == 0) {
        redf[w] = s;
        redk[w] = wmax;
        redi[w] = w * 32 + (__ffs(ball) - 1);
    }
    __syncthreads();                       // B3

    // ---- every warp combines -> Sf, kstar in registers ----
    float Sf;
    int   kstar;
    {
        float    Zv = (lane < 8) ? redf[lane] : 0.f;
        unsigned kv = (lane < 8) ? redk[lane] : 0u;
        int      ri = (lane < 8) ? redi[lane] : 0;
        #pragma unroll
        for (int off = 16; off; off >>= 1) Zv += __shfl_xor_sync(0xffffffffu, Zv, off);
        Sf = Zv;
        unsigned mx = __reduce_max_sync(0xffffffffu, kv);
        unsigned bl = __ballot_sync(0xffffffffu, kv == mx);
        int srcw = __ffs(bl) - 1;
        kstar = __shfl_sync(0xffffffffu, ri, srcw);
    }

    // ---- warp 0: rank-1 update E' = E * e^{delta_kstar W[kstar,:]}, ratio R ----
    if (w == 0) {
        float xks = xs[kstar];
        const float2* t2 = (const float2*)((xks == 0.0f) ? g_ewp : g_ewm);
        float2 pr = __ldg(&t2[(lane >> 1) * DD + kstar]);
        float mj  = (lane & 1) ? pr.y : pr.x;
        float E2  = E * mj;
        sE2[lane] = E2;
        float r = (1.f + E2) / (1.f + E);   // ratio (1+E')/(1+E)
        #pragma unroll
        for (int off = 16; off; off >>= 1) r *= __shfl_xor_sync(0xffffffffu, r, off);
        if (lane == 0) sRt = r;             // R = prod_j ratio
    }
    __syncthreads();                       // B4

    // ---- reverse pass: same cached e-values except thread kstar (sign flips) ----
    if (k == kstar) {
        const float2* o = (const float2*)((xk == 0.0f) ? g_ewm : g_ewp);
        #pragma unroll
        for (int jp = 0; jp < 16; ++jp) ec[jp] = __ldg(&o[jp * DD + k]);
    }
    const float eb2 = (k == kstar) ? ((xk == 0.0f) ? ebv.y : ebv.x) : eb;
    const float4* sE42 = (const float4*)sE2;

    float q0 = 1.f, q1 = 1.f, q2 = 1.f, q3 = 1.f;
    #pragma unroll
    for (int jp = 0; jp < 16; jp += 2) {
        float4 Ev = sE42[jp >> 1];
        q0 *= fmaf(Ev.x, ec[jp].x,     1.f);
        q1 *= fmaf(Ev.y, ec[jp].y,     1.f);
        q2 *= fmaf(Ev.z, ec[jp + 1].x, 1.f);
        q3 *= fmaf(Ev.w, ec[jp + 1].y, 1.f);
    }
    float q   = (q0 * q1) * (q2 * q3);
    float ek2 = eb2 * sqrtf(q);

    float s2 = ek2;
    #pragma unroll
    for (int off = 16; off; off >>= 1) s2 += __shfl_xor_sync(0xffffffffu, s2, off);
    if (lane == 0) redf[w] = s2;
    __syncthreads();                       // B5

    float Sr;
    {
        float Zv = (lane < 8) ? redf[lane] : 0.f;
        #pragma unroll
        for (int off = 16; off; off >>= 1) Zv += __shfl_xor_sync(0xffffffffu, Zv, off);
        Sr = Zv;
    }

    // ---- accept: Zf/Zr = sqrt(R) * Sf / Sr > u ----
    bool  accv  = sqrtf(sRt) * Sf > au * Sr;
    float out_k = (k == kstar && accv) ? (1.f - xk) : xk;
    out[row * DD + k] = out_k;
}

extern "C" void kernel_launch(void* const* d_in, const int* in_sizes, int n_in,
                              void* d_out, int out_size) {
    const float* x   = (const float*)d_in[0];
    const float* W   = (const float*)d_in[1];
    const float* b   = (const float*)d_in[2];
    const float* c   = (const float*)d_in[3];
    const float* gum = (const float*)d_in[4];
    const float* acc = (const float*)d_in[5];
    float* out = (float*)d_out;

    precompute_kernel<<<(DD * HH + 255) / 256, 256>>>(W, b);
    gwg_kernel<<<BB, 256>>>(x, W, c, gum, acc, out);
}

// round 5
// speedup vs baseline: 1.1790x; 1.0089x over previous
#include <cuda_runtime.h>

#define BB 1024
#define DD 256
#define HH 32

// exp(+W)/exp(-W), interleaved by j-pair: float2 element [pr*DD + d] holds
// (exp(s*W[d, 2*pr]), exp(s*W[d, 2*pr+1])) -> one coalesced LDG.64 per 2 factors.
__device__ float g_ewp[HH * DD];
__device__ float g_ewm[HH * DD];
__device__ float2 g_eb[DD];          // (exp(+b/2), exp(-b/2))

__global__ void precompute_kernel(const float* __restrict__ W,
                                  const float* __restrict__ b) {
    int i = blockIdx.x * blockDim.x + threadIdx.x;
    if (i < DD * HH) {
        int d = i >> 5;
        int j = i & 31;
        float w = W[i];
        int idx = (j >> 1) * (DD * 2) + d * 2 + (j & 1);
        g_ewp[idx] = expf(w);
        g_ewm[idx] = expf(-w);
    }
    if (i < DD) {
        float bv = b[i];
        g_eb[i] = make_float2(expf(0.5f * bv), expf(-0.5f * bv));
    }
}

__global__ __launch_bounds__(128, 7) void gwg_kernel(
    const float* __restrict__ x,
    const float* __restrict__ W,
    const float* __restrict__ c,
    const float* __restrict__ gum,
    const float* __restrict__ acc,
    float* __restrict__ out)
{
    __shared__ float  xs[DD];
    __shared__ float  ap[4][32];
    __shared__ __align__(16) float sEf[HH];   // E_j  = exp(a_j)
    __shared__ __align__(16) float sE2[HH];   // E'_j after rank-1 update
    __shared__ float sredf[4];
    __shared__ float sredkey[4];
    __shared__ int   sredi[4];
    __shared__ float sRt;

    const int row  = blockIdx.x;
    const int tid  = threadIdx.x;
    const int w    = tid >> 5;
    const int lane = tid & 31;
    const int k0   = tid;          // dims tid and tid+128
    const int k1   = tid + 128;

    float  xk0 = x[row * DD + k0];
    float  xk1 = x[row * DD + k1];
    float2 eb0 = g_eb[k0];
    float2 eb1 = g_eb[k1];
    float  u0  = gum[row * DD + k0];
    float  u1  = gum[row * DD + k1];
    float  au  = acc[row];
    xs[k0] = xk0;
    xs[k1] = xk1;

    // ---- a_j partials: warp w covers exactly the dims its threads hold:
    //      d in [32w, 32w+32) (xk0) and [32w+128, 32w+160) (xk1). lane = j.
    {
        unsigned m0 = __ballot_sync(0xffffffffu, xk0 != 0.0f);
        unsigned m1 = __ballot_sync(0xffffffffu, xk1 != 0.0f);
        const float* Wb0 = W + (w * 32) * HH + lane;
        const float* Wb1 = Wb0 + 128 * HH;
        float pa = 0.f, pb = 0.f;
        #pragma unroll
        for (int i = 0; i < 32; ++i) {
            if (m0 & (1u << i)) pa += Wb0[i * HH];
            if (m1 & (1u << i)) pb += Wb1[i * HH];
        }
        ap[w][lane] = pa + pb;
    }
    __syncthreads();                       // B1

    float E = 0.f;                         // exp(a_lane), warp 0 only
    if (w == 0) {
        float a = c[lane] + ap[0][lane] + ap[1][lane] + ap[2][lane] + ap[3][lane];
        E = expf(a);
        sEf[lane] = E;
    }
    __syncthreads();                       // B2

    // ---- forward: p~_k = prod_j (1 + E_j e^{delta_k w_kj});  ek = eb * sqrt ----
    const float2* t0 = (const float2*)((xk0 == 0.0f) ? g_ewp : g_ewm);
    const float2* t1 = (const float2*)((xk1 == 0.0f) ? g_ewp : g_ewm);
    const float ebf0 = (xk0 == 0.0f) ? eb0.x : eb0.y;
    const float ebf1 = (xk1 == 0.0f) ? eb1.x : eb1.y;
    const float4* sE4f = (const float4*)sEf;

    float p0 = 1.f, p1 = 1.f, p2 = 1.f, p3 = 1.f;
    float r0 = 1.f, r1 = 1.f, r2 = 1.f, r3 = 1.f;
    #pragma unroll
    for (int jp = 0; jp < 16; jp += 2) {
        float4 Ev = sE4f[jp >> 1];
        float2 aA = __ldg(&t0[jp * DD + k0]);
        float2 aB = __ldg(&t0[(jp + 1) * DD + k0]);
        float2 bA = __ldg(&t1[jp * DD + k1]);
        float2 bB = __ldg(&t1[(jp + 1) * DD + k1]);
        p0 *= fmaf(Ev.x, aA.x, 1.f);
        p1 *= fmaf(Ev.y, aA.y, 1.f);
        p2 *= fmaf(Ev.z, aB.x, 1.f);
        p3 *= fmaf(Ev.w, aB.y, 1.f);
        r0 *= fmaf(Ev.x, bA.x, 1.f);
        r1 *= fmaf(Ev.y, bA.y, 1.f);
        r2 *= fmaf(Ev.z, bB.x, 1.f);
        r3 *= fmaf(Ev.w, bB.y, 1.f);
    }
    float ek0 = ebf0 * sqrtf((p0 * p1) * (p2 * p3));
    float ek1 = ebf1 * sqrtf((r0 * r1) * (r2 * r3));

    // gumbel-max in exp domain: argmax(l+g) == argmax(ek / z); keys > 0
    float z0 = -logf(u0 + 1e-9f) + 1e-9f;
    float z1 = -logf(u1 + 1e-9f) + 1e-9f;
    float key0 = ek0 / z0;
    float key1 = ek1 / z1;

    // local pair (tie -> k0 since k0 < k1), then warp argmax/sum
    float key; int ki;
    if (key0 >= key1) { key = key0; ki = k0; } else { key = key1; ki = k1; }
    float s = ek0 + ek1;
    #pragma unroll
    for (int off = 16; off; off >>= 1) {
        s += __shfl_xor_sync(0xffffffffu, s, off);
        float ov = __shfl_xor_sync(0xffffffffu, key, off);
        int   oi = __shfl_xor_sync(0xffffffffu, ki,  off);
        if (ov > key || (ov == key && oi < ki)) { key = ov; ki = oi; }
    }
    if (lane == 0) { sredf[w] = s; sredkey[w] = key; sredi[w] = ki; }
    __syncthreads();                       // B3

    // ---- every warp combines 4 partials -> Sf, kstar in registers ----
    float Sf; int kstar;
    {
        float Zv = (lane < 4) ? sredf[lane]   : 0.f;
        float kv = (lane < 4) ? sredkey[lane] : -1.f;   // keys > 0
        int   ri = (lane < 4) ? sredi[lane]   : 0x7fffffff;
        #pragma unroll
        for (int off = 16; off; off >>= 1) {
            Zv += __shfl_xor_sync(0xffffffffu, Zv, off);
            float ov = __shfl_xor_sync(0xffffffffu, kv, off);
            int   oi = __shfl_xor_sync(0xffffffffu, ri, off);
            if (ov > kv || (ov == kv && oi < ri)) { kv = ov; ri = oi; }
        }
        Sf = Zv;
        kstar = ri;
    }

    // ---- warp 0: rank-1 update E' = E * e^{delta_kstar W[kstar,:]}, ratio R ----
    if (w == 0) {
        float xks = xs[kstar];
        const float2* t2 = (const float2*)((xks == 0.0f) ? g_ewp : g_ewm);
        float2 pr = __ldg(&t2[(lane >> 1) * DD + kstar]);
        float mj  = (lane & 1) ? pr.y : pr.x;
        float E2  = E * mj;
        sE2[lane] = E2;
        float r = (1.f + E2) / (1.f + E);
        #pragma unroll
        for (int off = 16; off; off >>= 1) r *= __shfl_xor_sync(0xffffffffu, r, off);
        if (lane == 0) sRt = r;
    }
    __syncthreads();                       // B4

    // ---- reverse pass at x_delta: tables flip only for the kstar dim ----
    const float2* t0r = (k0 == kstar) ? ((xk0 == 0.0f) ? (const float2*)g_ewm : (const float2*)g_ewp) : t0;
    const float2* t1r = (k1 == kstar) ? ((xk1 == 0.0f) ? (const float2*)g_ewm : (const float2*)g_ewp) : t1;
    const float ebr0 = (k0 == kstar) ? ((xk0 == 0.0f) ? eb0.y : eb0.x) : ebf0;
    const float ebr1 = (k1 == kstar) ? ((xk1 == 0.0f) ? eb1.y : eb1.x) : ebf1;
    const float4* sE42 = (const float4*)sE2;

    float q0 = 1.f, q1 = 1.f, q2 = 1.f, q3 = 1.f;
    float v0 = 1.f, v1 = 1.f, v2 = 1.f, v3 = 1.f;
    #pragma unroll
    for (int jp = 0; jp < 16; jp += 2) {
        float4 Ev = sE42[jp >> 1];
        float2 aA = __ldg(&t0r[jp * DD + k0]);
        float2 aB = __ldg(&t0r[(jp + 1) * DD + k0]);
        float2 bA = __ldg(&t1r[jp * DD + k1]);
        float2 bB = __ldg(&t1r[(jp + 1) * DD + k1]);
        q0 *= fmaf(Ev.x, aA.x, 1.f);
        q1 *= fmaf(Ev.y, aA.y, 1.f);
        q2 *= fmaf(Ev.z, aB.x, 1.f);
        q3 *= fmaf(Ev.w, aB.y, 1.f);
        v0 *= fmaf(Ev.x, bA.x, 1.f);
        v1 *= fmaf(Ev.y, bA.y, 1.f);
        v2 *= fmaf(Ev.z, bB.x, 1.f);
        v3 *= fmaf(Ev.w, bB.y, 1.f);
    }
    float er0 = ebr0 * sqrtf((q0 * q1) * (q2 * q3));
    float er1 = ebr1 * sqrtf((v0 * v1) * (v2 * v3));

    float s2 = er0 + er1;
    #pragma unroll
    for (int off = 16; off; off >>= 1) s2 += __shfl_xor_sync(0xffffffffu, s2, off);
    if (lane == 0) sredf[w] = s2;
    __syncthreads();                       // B5

    float Sr;
    {
        float Zv = (lane < 4) ? sredf[lane] : 0.f;
        #pragma unroll
        for (int off = 16; off; off >>= 1) Zv += __shfl_xor_sync(0xffffffffu, Zv, off);
        Sr = Zv;
    }

    // ---- accept: Zf/Zr = sqrt(R) * Sf / Sr > u ----
    bool accv = sqrtf(sRt) * Sf > au * Sr;
    out[row * DD + k0] = (k0 == kstar && accv) ? (1.f - xk0) : xk0;
    out[row * DD + k1] = (k1 == kstar && accv) ? (1.f - xk1) : xk1;
}

extern "C" void kernel_launch(void* const* d_in, const int* in_sizes, int n_in,
                              void* d_out, int out_size) {
    const float* x   = (const float*)d_in[0];
    const float* W   = (const float*)d_in[1];
    const float* b   = (const float*)d_in[2];
    const float* c   = (const float*)d_in[3];
    const float* gum = (const float*)d_in[4];
    const float* acc = (const float*)d_in[5];
    float* out = (float*)d_out;

    precompute_kernel<<<(DD * HH + 255) / 256, 256>>>(W, b);
    gwg_kernel<<<BB, 128>>>(x, W, c, gum, acc, out);
}